// round 16
// baseline (speedup 1.0000x reference)
#include <cuda_runtime.h>
#include <cuda_fp16.h>
#include <cstdint>

// ---------------- static problem config ----------------
#define T 4096
#define H 1024
#define F 2048
#define E 32
#define KSEL 2
#define CAP 512
#define AUX_COEF 0.01f

// ---------------- device scratch ----------------
__device__ float  g_probs[T * E];
__device__ int    g_top1[T];
__device__ int    g_route_e[T * KSEL];
__device__ float  g_route_w[T * KSEL];
__device__ int    g_route_pos[T * KSEL];
__device__ int    g_route_keep[T * KSEL];
__device__ int    g_count[E];
__device__ __half g_buf[(size_t)E * CAP * H];
__device__ __half g_hid[(size_t)E * CAP * F];
__device__ float  g_y[(size_t)E * CAP * H];
__device__ float  g_y2[(size_t)E * CAP * H];

// ---------------- helpers ----------------
__device__ __forceinline__ uint32_t smem_u32(const void* p) {
    uint32_t a;
    asm("{ .reg .u64 t; cvta.to.shared.u64 t, %1; cvt.u32.u64 %0, t; }" : "=r"(a) : "l"(p));
    return a;
}
__device__ __forceinline__ uint32_t packh2(float lo, float hi) {
    __half2 h = __floats2half2_rn(lo, hi);
    return *(uint32_t*)&h;
}
#define STS128(ad, a0, a1, a2, a3) \
    asm volatile("st.shared.v4.b32 [%0], {%1,%2,%3,%4};" :: "r"(ad), "r"(a0), "r"(a1), "r"(a2), "r"(a3) : "memory")
#define LDSM4(r0, r1, r2, r3, ad) \
    asm volatile("ldmatrix.sync.aligned.m8n8.x4.shared.b16 {%0,%1,%2,%3}, [%4];" \
        : "=r"(r0), "=r"(r1), "=r"(r2), "=r"(r3) : "r"(ad))
#define MMA16(d, a, b0v, b1v) \
    asm volatile("mma.sync.aligned.m16n8k16.row.col.f32.f16.f16.f32 " \
        "{%0,%1,%2,%3}, {%4,%5,%6,%7}, {%8,%9}, {%0,%1,%2,%3};" \
        : "+f"(d[0]), "+f"(d[1]), "+f"(d[2]), "+f"(d[3]) \
        : "r"(a[0]), "r"(a[1]), "r"(a[2]), "r"(a[3]), "r"(b0v), "r"(b1v))
#define CP16(dst, src) \
    asm volatile("cp.async.cg.shared.global [%0], [%1], 16;" :: "r"(dst), "l"(src) : "memory")
#define CP_COMMIT() asm volatile("cp.async.commit_group;" ::: "memory")
#define CP_WAIT0()  asm volatile("cp.async.wait_group 0;" ::: "memory")

// 128B-row swizzle: 8 chunks of 16B; phys chunk = c ^ (row & 7)
__device__ __forceinline__ uint32_t sw128(uint32_t row, uint32_t c) {
    return row * 128 + ((c ^ (row & 7)) * 16);
}

// ---------------- router: 16 tokens/block ----------------
#define RT 16
__global__ void __launch_bounds__(256) router_kernel(const float* __restrict__ x,
                                                     const float* __restrict__ Wr,
                                                     const float* __restrict__ br) {
    extern __shared__ float xs[];
    __shared__ float sl[RT * E];
    int tid = threadIdx.x;
    int tb = blockIdx.x * RT;

    const float4* xp = (const float4*)x + (size_t)tb * (H / 4);
    float4* xsp = (float4*)xs;
    #pragma unroll
    for (int i = 0; i < RT; i++)
        xsp[tid + i * 256] = xp[tid + i * 256];
    __syncthreads();

    int e = tid >> 3, r = tid & 7;
    float acc[RT];
    #pragma unroll
    for (int t = 0; t < RT; t++) acc[t] = 0.f;
    const float4* wp = (const float4*)(Wr + (size_t)e * H) + r;
    #pragma unroll 4
    for (int h8 = 0; h8 < H / 32; h8++) {
        float4 w = wp[h8 * 8];
        #pragma unroll
        for (int t = 0; t < RT; t++) {
            float4 xv = xsp[t * 256 + h8 * 8 + r];
            acc[t] += w.x * xv.x + w.y * xv.y + w.z * xv.z + w.w * xv.w;
        }
    }
    float be = br[e];
    #pragma unroll
    for (int t = 0; t < RT; t++) {
        float a = acc[t];
        a += __shfl_down_sync(0xffffffffu, a, 4, 8);
        a += __shfl_down_sync(0xffffffffu, a, 2, 8);
        a += __shfl_down_sync(0xffffffffu, a, 1, 8);
        if (r == 0) sl[t * E + e] = a + be;
    }
    __syncthreads();

    int wid = tid >> 5, lane = tid & 31;
    #pragma unroll
    for (int tt = 0; tt < 2; tt++) {
        int tl = wid * 2 + tt;
        int t = tb + tl;
        float l = sl[tl * E + lane];
        float m = l;
        #pragma unroll
        for (int o = 16; o; o >>= 1) m = fmaxf(m, __shfl_xor_sync(0xffffffffu, m, o));
        float p = __expf(l - m);
        float s = p;
        #pragma unroll
        for (int o = 16; o; o >>= 1) s += __shfl_xor_sync(0xffffffffu, s, o);
        p = p / s;
        g_probs[(size_t)t * E + lane] = p;
        float p1 = p; int i1 = lane;
        #pragma unroll
        for (int o = 16; o; o >>= 1) {
            float op = __shfl_xor_sync(0xffffffffu, p1, o);
            int   oi = __shfl_xor_sync(0xffffffffu, i1, o);
            if (op > p1 || (op == p1 && oi < i1)) { p1 = op; i1 = oi; }
        }
        float pm = (lane == i1) ? -1.f : p;
        float p2 = pm; int i2 = lane;
        #pragma unroll
        for (int o = 16; o; o >>= 1) {
            float op = __shfl_xor_sync(0xffffffffu, p2, o);
            int   oi = __shfl_xor_sync(0xffffffffu, i2, o);
            if (op > p2 || (op == p2 && oi < i2)) { p2 = op; i2 = oi; }
        }
        if (lane == 0) {
            g_top1[t] = i1;
            float mx = fmaxf(p1, p2);
            float e1 = __expf(p1 - mx), e2 = __expf(p2 - mx);
            float inv = 1.f / (e1 + e2);
            g_route_e[2 * t]     = i1; g_route_w[2 * t]     = e1 * inv;
            g_route_e[2 * t + 1] = i2; g_route_w[2 * t + 1] = e2 * inv;
        }
    }
}

// ---------------- dispatch ----------------
__global__ void dispatch_kernel() {
    __shared__ int se[T * KSEL];
    int tid = threadIdx.x;
    for (int i = tid; i < T * KSEL; i += 1024) se[i] = g_route_e[i];
    __syncthreads();
    int warp = tid >> 5, lane = tid & 31;
    int base = 0;
    for (int c = 0; c < T * KSEL; c += 32) {
        int e = se[c + lane];
        unsigned m = __ballot_sync(0xffffffffu, e == warp);
        if (e == warp) {
            int pos = base + __popc(m & ((1u << lane) - 1u));
            g_route_pos[c + lane]  = pos;
            g_route_keep[c + lane] = (pos < CAP) ? 1 : 0;
        }
        base += __popc(m);
    }
    if (lane == 0) g_count[warp] = (base < CAP) ? base : CAP;
}

// ---------------- gather ----------------
__global__ void gather_kernel(const float* __restrict__ x) {
    int i = blockIdx.x;
    if (!g_route_keep[i]) return;
    int t = i >> 1;
    int e = g_route_e[i], pos = g_route_pos[i];
    __half* dst = g_buf + ((size_t)e * CAP + pos) * H;
    const float* src = x + (size_t)t * H;
    int h = threadIdx.x * 4;
    float4 v = *(const float4*)(src + h);
    uint2 o;
    o.x = packh2(v.x, v.y);
    o.y = packh2(v.z, v.w);
    *(uint2*)(dst + h) = o;
}

// ---------------- fused gate/up GEMM + SwiGLU: M-tile 64, 2 CTAs/SM ----------------
// Block 64(M)x128(N), 256 thr / 8 warps (2m x 4n), warp 32x32 per matrix, KCH=64.
#define GU_AST (64 * 128)            // 8KB A
#define GU_BST (128 * 128)           // 16KB per B
#define GU_STG (GU_AST + 2 * GU_BST) // 40KB/stage
#define DN_AST (128 * 128)           // 16KB A
#define DN_BST (128 * 128)           // 16KB B
#define DN_STG (DN_AST + DN_BST)     // 32KB/stage

// compute one ks block of the gu mainloop
#define GU_KS_BLOCK(ksv) do { \
    uint32_t a[2][4], bg[2][4], bu[2][4]; \
    _Pragma("unroll") \
    for (int i = 0; i < 2; i++) \
        LDSM4(a[i][0], a[i][1], a[i][2], a[i][3], SA + sw128(a_r + i * 16, (ksv) * 2 + chi)); \
    _Pragma("unroll") \
    for (int j = 0; j < 2; j++) { \
        LDSM4(bg[j][0], bg[j][1], bg[j][2], bg[j][3], SBG + sw128(b_r + j * 16, (ksv) * 2 + chi)); \
        LDSM4(bu[j][0], bu[j][1], bu[j][2], bu[j][3], SBU + sw128(b_r + j * 16, (ksv) * 2 + chi)); \
    } \
    _Pragma("unroll") \
    for (int i = 0; i < 2; i++) \
        _Pragma("unroll") \
        for (int j4 = 0; j4 < 4; j4++) { \
            MMA16(accG[i][j4], a[i], bg[j4 >> 1][j4 & 1], bg[j4 >> 1][(j4 & 1) + 2]); \
            MMA16(accU[i][j4], a[i], bu[j4 >> 1][j4 & 1], bu[j4 >> 1][(j4 & 1) + 2]); \
        } \
} while (0)

__global__ void __launch_bounds__(256, 2) gu_mma(const float* __restrict__ Wg,
                                                 const float* __restrict__ Wu) {
    extern __shared__ char smem[];
    int e = blockIdx.z, cnt = g_count[e];
    int m0 = blockIdx.y * 64;
    if (m0 >= cnt) return;
    int n0 = blockIdx.x * 128;
    uint32_t sbuf = (smem_u32(smem) + 127u) & ~127u;

    int tid = threadIdx.x, lane = tid & 31, wid = tid >> 5;
    int wm = wid >> 2, wn = wid & 3;

    const __half* A = g_buf + (size_t)e * CAP * H + (size_t)m0 * H;
    const float* G = Wg + (size_t)e * H * F + n0;
    const float* U = Wu + (size_t)e * H * F + n0;

    int arow = tid >> 2, ac = (tid & 3) * 2;   // A: row 0..63, 2 chunks
    int bn = tid & 127, kh = tid >> 7;         // B: n-row, k-eighth (kh in 0..1)
    uint32_t a_r = wm * 32 + (lane & 15);
    uint32_t b_r = wn * 32 + (lane & 15);
    uint32_t chi = lane >> 4;

    float accG[2][4][4] = {};
    float accU[2][4][4] = {};
    uint32_t rbA[8], rbB[8];

    const int NS = H / 64;   // 16
    // ---- prologue: stage 0 ----
    {
        uint32_t SA = sbuf, SBG = SA + GU_AST, SBU = SBG + GU_BST;
        CP16(SA + sw128(arow, ac),     A + (size_t)arow * H + ac * 8);
        CP16(SA + sw128(arow, ac + 1), A + (size_t)arow * H + ac * 8 + 8);
        CP_COMMIT();
        #pragma unroll
        for (int q = 0; q < 8; q++)
            rbA[q] = packh2(G[(size_t)(kh * 16 + 2 * q) * F + bn], G[(size_t)(kh * 16 + 2 * q + 1) * F + bn]);
        STS128(SBG + sw128(bn, kh * 2),     rbA[0], rbA[1], rbA[2], rbA[3]);
        STS128(SBG + sw128(bn, kh * 2 + 1), rbA[4], rbA[5], rbA[6], rbA[7]);
        #pragma unroll
        for (int q = 0; q < 8; q++)
            rbA[q] = packh2(G[(size_t)(32 + kh * 16 + 2 * q) * F + bn], G[(size_t)(33 + kh * 16 + 2 * q) * F + bn]);
        STS128(SBG + sw128(bn, 4 + kh * 2), rbA[0], rbA[1], rbA[2], rbA[3]);
        STS128(SBG + sw128(bn, 5 + kh * 2), rbA[4], rbA[5], rbA[6], rbA[7]);
        #pragma unroll
        for (int q = 0; q < 8; q++)
            rbA[q] = packh2(U[(size_t)(kh * 16 + 2 * q) * F + bn], U[(size_t)(kh * 16 + 2 * q + 1) * F + bn]);
        STS128(SBU + sw128(bn, kh * 2),     rbA[0], rbA[1], rbA[2], rbA[3]);
        STS128(SBU + sw128(bn, kh * 2 + 1), rbA[4], rbA[5], rbA[6], rbA[7]);
        #pragma unroll
        for (int q = 0; q < 8; q++)
            rbA[q] = packh2(U[(size_t)(32 + kh * 16 + 2 * q) * F + bn], U[(size_t)(33 + kh * 16 + 2 * q) * F + bn]);
        STS128(SBU + sw128(bn, 4 + kh * 2), rbA[0], rbA[1], rbA[2], rbA[3]);
        STS128(SBU + sw128(bn, 5 + kh * 2), rbA[4], rbA[5], rbA[6], rbA[7]);
        CP_WAIT0();
        __syncthreads();
    }

    for (int s = 0; s < NS; s++) {
        uint32_t SA = sbuf + (s & 1) * GU_STG;
        uint32_t SBG = SA + GU_AST, SBU = SBG + GU_BST;
        uint32_t SAn = sbuf + ((s + 1) & 1) * GU_STG;
        uint32_t SBGn = SAn + GU_AST, SBUn = SBGn + GU_BST;
        int k0 = (s + 1) * 64;

        if (s + 1 < NS) {
            CP16(SAn + sw128(arow, ac),     A + (size_t)arow * H + k0 + ac * 8);
            CP16(SAn + sw128(arow, ac + 1), A + (size_t)arow * H + k0 + ac * 8 + 8);
            CP_COMMIT();
            #pragma unroll
            for (int q = 0; q < 8; q++)
                rbA[q] = packh2(G[(size_t)(k0 + kh * 16 + 2 * q) * F + bn], G[(size_t)(k0 + kh * 16 + 2 * q + 1) * F + bn]);
        }
        GU_KS_BLOCK(0);
        if (s + 1 < NS) {
            #pragma unroll
            for (int q = 0; q < 8; q++)
                rbB[q] = packh2(G[(size_t)(k0 + 32 + kh * 16 + 2 * q) * F + bn], G[(size_t)(k0 + 33 + kh * 16 + 2 * q) * F + bn]);
        }
        GU_KS_BLOCK(1);
        if (s + 1 < NS) {
            STS128(SBGn + sw128(bn, kh * 2),     rbA[0], rbA[1], rbA[2], rbA[3]);
            STS128(SBGn + sw128(bn, kh * 2 + 1), rbA[4], rbA[5], rbA[6], rbA[7]);
            #pragma unroll
            for (int q = 0; q < 8; q++)
                rbA[q] = packh2(U[(size_t)(k0 + kh * 16 + 2 * q) * F + bn], U[(size_t)(k0 + kh * 16 + 2 * q + 1) * F + bn]);
        }
        GU_KS_BLOCK(2);
        if (s + 1 < NS) {
            STS128(SBGn + sw128(bn, 4 + kh * 2), rbB[0], rbB[1], rbB[2], rbB[3]);
            STS128(SBGn + sw128(bn, 5 + kh * 2), rbB[4], rbB[5], rbB[6], rbB[7]);
            #pragma unroll
            for (int q = 0; q < 8; q++)
                rbB[q] = packh2(U[(size_t)(k0 + 32 + kh * 16 + 2 * q) * F + bn], U[(size_t)(k0 + 33 + kh * 16 + 2 * q) * F + bn]);
        }
        GU_KS_BLOCK(3);
        if (s + 1 < NS) {
            STS128(SBUn + sw128(bn, kh * 2),     rbA[0], rbA[1], rbA[2], rbA[3]);
            STS128(SBUn + sw128(bn, kh * 2 + 1), rbA[4], rbA[5], rbA[6], rbA[7]);
            STS128(SBUn + sw128(bn, 4 + kh * 2), rbB[0], rbB[1], rbB[2], rbB[3]);
            STS128(SBUn + sw128(bn, 5 + kh * 2), rbB[4], rbB[5], rbB[6], rbB[7]);
        }
        CP_WAIT0();
        __syncthreads();
    }

    __half* Hd = g_hid + (size_t)e * CAP * F;
    int r0 = m0 + wm * 32 + (lane >> 2);
    int c0 = n0 + wn * 32 + (lane & 3) * 2;
    #pragma unroll
    for (int i = 0; i < 2; i++) {
        #pragma unroll
        for (int j = 0; j < 4; j++) {
            int r = r0 + i * 16, c = c0 + j * 8;
            if (r < cnt) {
                float g0 = accG[i][j][0], g1 = accG[i][j][1];
                *(uint32_t*)(Hd + (size_t)r * F + c) =
                    packh2(g0 / (1.f + __expf(-g0)) * accU[i][j][0],
                           g1 / (1.f + __expf(-g1)) * accU[i][j][1]);
            }
            if (r + 8 < cnt) {
                float g2 = accG[i][j][2], g3 = accG[i][j][3];
                *(uint32_t*)(Hd + (size_t)(r + 8) * F + c) =
                    packh2(g2 / (1.f + __expf(-g2)) * accU[i][j][2],
                           g3 / (1.f + __expf(-g3)) * accU[i][j][3]);
            }
        }
    }
}

// ---------------- down GEMM: warp 64x32, 2 CTAs/SM, split-K=2 (R13) ----------------
__global__ void __launch_bounds__(256, 2) down_mma(const float* __restrict__ Wd) {
    extern __shared__ char smem[];
    int e = blockIdx.z >> 1, kz = blockIdx.z & 1;
    int cnt = g_count[e];
    int m0 = blockIdx.y * 128;
    if (m0 >= cnt) return;
    int n0 = blockIdx.x * 128;
    uint32_t sbuf = (smem_u32(smem) + 127u) & ~127u;

    int tid = threadIdx.x, lane = tid & 31, wid = tid >> 5;
    int wm = wid >> 2, wn = wid & 3;

    const __half* A = g_hid + ((size_t)e * CAP + m0) * F + kz * (F / 2);
    const float*  W = Wd + (size_t)e * F * H + (size_t)kz * (F / 2) * H + n0;

    int arow = tid >> 1, ac = (tid & 1) * 4;
    int bn = tid & 127, kh = tid >> 7;
    uint32_t a_r = wm * 64 + (lane & 15);
    uint32_t b_r = wn * 32 + (lane & 15);
    uint32_t chi = lane >> 4;

    float acc[4][4][4] = {};
    uint32_t rb[8];

    const int NS = (F / 2) / 64;   // 16
    {
        uint32_t SA = sbuf, SB = SA + DN_AST;
        #pragma unroll
        for (int q = 0; q < 4; q++)
            CP16(SA + sw128(arow, ac + q), A + (size_t)arow * F + (ac + q) * 8);
        CP_COMMIT();
        #pragma unroll
        for (int q = 0; q < 8; q++)
            rb[q] = packh2(W[(size_t)(kh * 32 + 2 * q) * H + bn], W[(size_t)(kh * 32 + 2 * q + 1) * H + bn]);
        STS128(SB + sw128(bn, kh * 4),     rb[0], rb[1], rb[2], rb[3]);
        STS128(SB + sw128(bn, kh * 4 + 1), rb[4], rb[5], rb[6], rb[7]);
        #pragma unroll
        for (int q = 0; q < 8; q++)
            rb[q] = packh2(W[(size_t)(kh * 32 + 16 + 2 * q) * H + bn], W[(size_t)(kh * 32 + 17 + 2 * q) * H + bn]);
        STS128(SB + sw128(bn, kh * 4 + 2), rb[0], rb[1], rb[2], rb[3]);
        STS128(SB + sw128(bn, kh * 4 + 3), rb[4], rb[5], rb[6], rb[7]);
        CP_WAIT0();
        __syncthreads();
    }

    #pragma unroll 2
    for (int s = 0; s < NS; s++) {
        uint32_t SA = sbuf + (s & 1) * DN_STG, SB = SA + DN_AST;
        uint32_t SAn = sbuf + ((s + 1) & 1) * DN_STG, SBn = SAn + DN_AST;
        int k0 = (s + 1) * 64;

        if (s + 1 < NS) {
            #pragma unroll
            for (int q = 0; q < 4; q++)
                CP16(SAn + sw128(arow, ac + q), A + (size_t)arow * F + k0 + (ac + q) * 8);
            CP_COMMIT();
            #pragma unroll
            for (int q = 0; q < 8; q++)
                rb[q] = packh2(W[(size_t)(k0 + kh * 32 + 2 * q) * H + bn], W[(size_t)(k0 + kh * 32 + 2 * q + 1) * H + bn]);
        }
        #pragma unroll
        for (int ks = 0; ks < 2; ks++) {
            uint32_t a[4][4], bq[2][4];
            #pragma unroll
            for (int i = 0; i < 4; i++)
                LDSM4(a[i][0], a[i][1], a[i][2], a[i][3], SA + sw128(a_r + i * 16, ks * 2 + chi));
            #pragma unroll
            for (int j = 0; j < 2; j++)
                LDSM4(bq[j][0], bq[j][1], bq[j][2], bq[j][3], SB + sw128(b_r + j * 16, ks * 2 + chi));
            #pragma unroll
            for (int i = 0; i < 4; i++)
                #pragma unroll
                for (int j4 = 0; j4 < 4; j4++)
                    MMA16(acc[i][j4], a[i], bq[j4 >> 1][j4 & 1], bq[j4 >> 1][(j4 & 1) + 2]);
        }
        if (s + 1 < NS) {
            STS128(SBn + sw128(bn, kh * 4),     rb[0], rb[1], rb[2], rb[3]);
            STS128(SBn + sw128(bn, kh * 4 + 1), rb[4], rb[5], rb[6], rb[7]);
            #pragma unroll
            for (int q = 0; q < 8; q++)
                rb[q] = packh2(W[(size_t)(k0 + kh * 32 + 16 + 2 * q) * H + bn], W[(size_t)(k0 + kh * 32 + 17 + 2 * q) * H + bn]);
        }
        #pragma unroll
        for (int ks = 2; ks < 4; ks++) {
            uint32_t a[4][4], bq[2][4];
            #pragma unroll
            for (int i = 0; i < 4; i++)
                LDSM4(a[i][0], a[i][1], a[i][2], a[i][3], SA + sw128(a_r + i * 16, ks * 2 + chi));
            #pragma unroll
            for (int j = 0; j < 2; j++)
                LDSM4(bq[j][0], bq[j][1], bq[j][2], bq[j][3], SB + sw128(b_r + j * 16, ks * 2 + chi));
            #pragma unroll
            for (int i = 0; i < 4; i++)
                #pragma unroll
                for (int j4 = 0; j4 < 4; j4++)
                    MMA16(acc[i][j4], a[i], bq[j4 >> 1][j4 & 1], bq[j4 >> 1][(j4 & 1) + 2]);
        }
        if (s + 1 < NS) {
            STS128(SBn + sw128(bn, kh * 4 + 2), rb[0], rb[1], rb[2], rb[3]);
            STS128(SBn + sw128(bn, kh * 4 + 3), rb[4], rb[5], rb[6], rb[7]);
        }
        CP_WAIT0();
        __syncthreads();
    }

    float* Y = (kz == 0 ? g_y : g_y2) + (size_t)e * CAP * H;
    int r0 = m0 + wm * 64 + (lane >> 2);
    int c0 = n0 + wn * 32 + (lane & 3) * 2;
    #pragma unroll
    for (int i = 0; i < 4; i++) {
        #pragma unroll
        for (int j = 0; j < 4; j++) {
            int r = r0 + i * 16, c = c0 + j * 8;
            if (r < cnt)
                *(float2*)(Y + (size_t)r * H + c) = make_float2(acc[i][j][0], acc[i][j][1]);
            if (r + 8 < cnt)
                *(float2*)(Y + (size_t)(r + 8) * H + c) = make_float2(acc[i][j][2], acc[i][j][3]);
        }
    }
}

// ---------------- combine (+ aux in extra block) ----------------
__global__ void combine_kernel(float* __restrict__ out, int do_aux) {
    if (blockIdx.x == T) {
        int tid = threadIdx.x, wid = tid >> 5, lane = tid & 31;
        __shared__ float part[E];
        #pragma unroll
        for (int ee = 0; ee < 4; ee++) {
            int e = wid * 4 + ee;
            float s = 0.f; int c = 0;
            for (int t = lane; t < T; t += 32) {
                s += g_probs[(size_t)t * E + e];
                c += (g_top1[t] == e) ? 1 : 0;
            }
            #pragma unroll
            for (int o = 16; o; o >>= 1) {
                s += __shfl_xor_sync(0xffffffffu, s, o);
                c += __shfl_xor_sync(0xffffffffu, c, o);
            }
            if (lane == 0) part[e] = (s / (float)T) * ((float)c / (float)T);
        }
        __syncthreads();
        if (tid == 0) {
            float a = 0.f;
            for (int i = 0; i < E; i++) a += part[i];
            out[(size_t)T * H] = a * (float)E * AUX_COEF;
        }
        return;
    }
    int t = blockIdx.x;
    int i0 = 2 * t, i1 = 2 * t + 1;
    int e0 = g_route_e[i0], e1 = g_route_e[i1];
    int k0 = g_route_keep[i0], k1 = g_route_keep[i1];
    int p0 = k0 ? g_route_pos[i0] : 0;
    int p1 = k1 ? g_route_pos[i1] : 0;
    float w0 = k0 ? g_route_w[i0] : 0.f;
    float w1 = k1 ? g_route_w[i1] : 0.f;
    size_t o0 = ((size_t)e0 * CAP + p0) * H;
    size_t o1 = ((size_t)e1 * CAP + p1) * H;
    float* o = out + (size_t)t * H;
    int h = threadIdx.x * 4;
    float4 a0 = *(const float4*)(g_y + o0 + h);
    float4 a1 = *(const float4*)(g_y2 + o0 + h);
    float4 b0 = *(const float4*)(g_y + o1 + h);
    float4 b1 = *(const float4*)(g_y2 + o1 + h);
    float4 r;
    r.x = w0 * (a0.x + a1.x) + w1 * (b0.x + b1.x);
    r.y = w0 * (a0.y + a1.y) + w1 * (b0.y + b1.y);
    r.z = w0 * (a0.z + a1.z) + w1 * (b0.z + b1.z);
    r.w = w0 * (a0.w + a1.w) + w1 * (b0.w + b1.w);
    *(float4*)(o + h) = r;
}

// ---------------- launch ----------------
extern "C" void kernel_launch(void* const* d_in, const int* in_sizes, int n_in,
                              void* d_out, int out_size) {
    const float* x  = (const float*)d_in[0];
    const float* Wr = (const float*)d_in[1];
    const float* br = (const float*)d_in[2];
    const float* Wg = (const float*)d_in[3];
    const float* Wu = (const float*)d_in[4];
    const float* Wd = (const float*)d_in[5];
    float* out = (float*)d_out;

    int gu_sm = 2 * GU_STG + 128;   // 80KB -> 2 CTAs/SM
    int dn_sm = 2 * DN_STG + 128;   // 64KB -> 2 CTAs/SM
    int rsm = RT * H * 4;
    cudaFuncSetAttribute(gu_mma, cudaFuncAttributeMaxDynamicSharedMemorySize, gu_sm);
    cudaFuncSetAttribute(down_mma, cudaFuncAttributeMaxDynamicSharedMemorySize, dn_sm);
    cudaFuncSetAttribute(router_kernel, cudaFuncAttributeMaxDynamicSharedMemorySize, rsm);

    router_kernel<<<T / RT, 256, rsm>>>(x, Wr, br);
    dispatch_kernel<<<1, 1024>>>();
    gather_kernel<<<T * KSEL, 256>>>(x);

    dim3 gu_grid(F / 128, CAP / 64, E);
    gu_mma<<<gu_grid, 256, gu_sm>>>(Wg, Wu);

    dim3 dn_grid(H / 128, CAP / 128, E * 2);
    down_mma<<<dn_grid, 256, dn_sm>>>(Wd);

    int do_aux = (out_size > T * H) ? 1 : 0;
    combine_kernel<<<T + do_aux, 256>>>(out, do_aux);
}

// round 17
// speedup vs baseline: 1.1097x; 1.1097x over previous
#include <cuda_runtime.h>
#include <cuda_fp16.h>
#include <cstdint>

// ---------------- static problem config ----------------
#define T 4096
#define H 1024
#define F 2048
#define E 32
#define KSEL 2
#define CAP 512
#define AUX_COEF 0.01f

// ---------------- device scratch ----------------
__device__ float  g_probs[T * E];
__device__ int    g_top1[T];
__device__ int    g_route_e[T * KSEL];
__device__ float  g_route_w[T * KSEL];
__device__ int    g_route_pos[T * KSEL];
__device__ int    g_route_keep[T * KSEL];
__device__ int    g_count[E];
__device__ __half g_buf[(size_t)E * CAP * H];
__device__ __half g_hid[(size_t)E * CAP * F];
__device__ __half g_yh[(size_t)E * CAP * H];    // split-K partial 0 (fp16)
__device__ __half g_yh2[(size_t)E * CAP * H];   // split-K partial 1 (fp16)

// ---------------- helpers ----------------
__device__ __forceinline__ uint32_t smem_u32(const void* p) {
    uint32_t a;
    asm("{ .reg .u64 t; cvta.to.shared.u64 t, %1; cvt.u32.u64 %0, t; }" : "=r"(a) : "l"(p));
    return a;
}
__device__ __forceinline__ uint32_t packh2(float lo, float hi) {
    __half2 h = __floats2half2_rn(lo, hi);
    return *(uint32_t*)&h;
}
#define STS128(ad, a0, a1, a2, a3) \
    asm volatile("st.shared.v4.b32 [%0], {%1,%2,%3,%4};" :: "r"(ad), "r"(a0), "r"(a1), "r"(a2), "r"(a3) : "memory")
#define LDSM4(r0, r1, r2, r3, ad) \
    asm volatile("ldmatrix.sync.aligned.m8n8.x4.shared.b16 {%0,%1,%2,%3}, [%4];" \
        : "=r"(r0), "=r"(r1), "=r"(r2), "=r"(r3) : "r"(ad))
#define MMA16(d, a, b0v, b1v) \
    asm volatile("mma.sync.aligned.m16n8k16.row.col.f32.f16.f16.f32 " \
        "{%0,%1,%2,%3}, {%4,%5,%6,%7}, {%8,%9}, {%0,%1,%2,%3};" \
        : "+f"(d[0]), "+f"(d[1]), "+f"(d[2]), "+f"(d[3]) \
        : "r"(a[0]), "r"(a[1]), "r"(a[2]), "r"(a[3]), "r"(b0v), "r"(b1v))
#define CP16(dst, src) \
    asm volatile("cp.async.cg.shared.global [%0], [%1], 16;" :: "r"(dst), "l"(src) : "memory")
#define CP_COMMIT() asm volatile("cp.async.commit_group;" ::: "memory")
#define CP_WAIT0()  asm volatile("cp.async.wait_group 0;" ::: "memory")

// 128B-row swizzle: 8 chunks of 16B; phys chunk = c ^ (row & 7)
__device__ __forceinline__ uint32_t sw128(uint32_t row, uint32_t c) {
    return row * 128 + ((c ^ (row & 7)) * 16);
}

// ---------------- router: 16 tokens/block ----------------
#define RT 16
__global__ void __launch_bounds__(256) router_kernel(const float* __restrict__ x,
                                                     const float* __restrict__ Wr,
                                                     const float* __restrict__ br) {
    extern __shared__ float xs[];
    __shared__ float sl[RT * E];
    int tid = threadIdx.x;
    int tb = blockIdx.x * RT;

    const float4* xp = (const float4*)x + (size_t)tb * (H / 4);
    float4* xsp = (float4*)xs;
    #pragma unroll
    for (int i = 0; i < RT; i++)
        xsp[tid + i * 256] = xp[tid + i * 256];
    __syncthreads();

    int e = tid >> 3, r = tid & 7;
    float acc[RT];
    #pragma unroll
    for (int t = 0; t < RT; t++) acc[t] = 0.f;
    const float4* wp = (const float4*)(Wr + (size_t)e * H) + r;
    #pragma unroll 4
    for (int h8 = 0; h8 < H / 32; h8++) {
        float4 w = wp[h8 * 8];
        #pragma unroll
        for (int t = 0; t < RT; t++) {
            float4 xv = xsp[t * 256 + h8 * 8 + r];
            acc[t] += w.x * xv.x + w.y * xv.y + w.z * xv.z + w.w * xv.w;
        }
    }
    float be = br[e];
    #pragma unroll
    for (int t = 0; t < RT; t++) {
        float a = acc[t];
        a += __shfl_down_sync(0xffffffffu, a, 4, 8);
        a += __shfl_down_sync(0xffffffffu, a, 2, 8);
        a += __shfl_down_sync(0xffffffffu, a, 1, 8);
        if (r == 0) sl[t * E + e] = a + be;
    }
    __syncthreads();

    int wid = tid >> 5, lane = tid & 31;
    #pragma unroll
    for (int tt = 0; tt < 2; tt++) {
        int tl = wid * 2 + tt;
        int t = tb + tl;
        float l = sl[tl * E + lane];
        float m = l;
        #pragma unroll
        for (int o = 16; o; o >>= 1) m = fmaxf(m, __shfl_xor_sync(0xffffffffu, m, o));
        float p = __expf(l - m);
        float s = p;
        #pragma unroll
        for (int o = 16; o; o >>= 1) s += __shfl_xor_sync(0xffffffffu, s, o);
        p = p / s;
        g_probs[(size_t)t * E + lane] = p;
        float p1 = p; int i1 = lane;
        #pragma unroll
        for (int o = 16; o; o >>= 1) {
            float op = __shfl_xor_sync(0xffffffffu, p1, o);
            int   oi = __shfl_xor_sync(0xffffffffu, i1, o);
            if (op > p1 || (op == p1 && oi < i1)) { p1 = op; i1 = oi; }
        }
        float pm = (lane == i1) ? -1.f : p;
        float p2 = pm; int i2 = lane;
        #pragma unroll
        for (int o = 16; o; o >>= 1) {
            float op = __shfl_xor_sync(0xffffffffu, p2, o);
            int   oi = __shfl_xor_sync(0xffffffffu, i2, o);
            if (op > p2 || (op == p2 && oi < i2)) { p2 = op; i2 = oi; }
        }
        if (lane == 0) {
            g_top1[t] = i1;
            float mx = fmaxf(p1, p2);
            float e1 = __expf(p1 - mx), e2 = __expf(p2 - mx);
            float inv = 1.f / (e1 + e2);
            g_route_e[2 * t]     = i1; g_route_w[2 * t]     = e1 * inv;
            g_route_e[2 * t + 1] = i2; g_route_w[2 * t + 1] = e2 * inv;
        }
    }
}

// ---------------- dispatch ----------------
__global__ void dispatch_kernel() {
    __shared__ int se[T * KSEL];
    int tid = threadIdx.x;
    for (int i = tid; i < T * KSEL; i += 1024) se[i] = g_route_e[i];
    __syncthreads();
    int warp = tid >> 5, lane = tid & 31;
    int base = 0;
    for (int c = 0; c < T * KSEL; c += 32) {
        int e = se[c + lane];
        unsigned m = __ballot_sync(0xffffffffu, e == warp);
        if (e == warp) {
            int pos = base + __popc(m & ((1u << lane) - 1u));
            g_route_pos[c + lane]  = pos;
            g_route_keep[c + lane] = (pos < CAP) ? 1 : 0;
        }
        base += __popc(m);
    }
    if (lane == 0) g_count[warp] = (base < CAP) ? base : CAP;
}

// ---------------- gather ----------------
__global__ void gather_kernel(const float* __restrict__ x) {
    int i = blockIdx.x;
    if (!g_route_keep[i]) return;
    int t = i >> 1;
    int e = g_route_e[i], pos = g_route_pos[i];
    __half* dst = g_buf + ((size_t)e * CAP + pos) * H;
    const float* src = x + (size_t)t * H;
    int h = threadIdx.x * 4;
    float4 v = *(const float4*)(src + h);
    uint2 o;
    o.x = packh2(v.x, v.y);
    o.y = packh2(v.z, v.w);
    *(uint2*)(dst + h) = o;
}

// ---------------- fused gate/up GEMM + SwiGLU, KCH=64 ----------------
#define GU_AST (128 * 128)           // 16KB per tile (A, BG, BU)
#define GU_STG (3 * GU_AST)          // 48KB/stage
#define DN_AST (128 * 128)           // 16KB A
#define DN_BST (128 * 128)           // 16KB B
#define DN_STG (DN_AST + DN_BST)     // 32KB/stage

__global__ void __launch_bounds__(512, 1) gu_mma(const float* __restrict__ Wg,
                                                 const float* __restrict__ Wu) {
    extern __shared__ char smem[];
    int e = blockIdx.z, cnt = g_count[e];
    int m0 = blockIdx.y * 128;
    if (m0 >= cnt) return;
    int n0 = blockIdx.x * 128;
    uint32_t sbuf = (smem_u32(smem) + 127u) & ~127u;

    int tid = threadIdx.x, lane = tid & 31, wid = tid >> 5;
    int wm = wid >> 2, wn = wid & 3;

    const __half* A = g_buf + (size_t)e * CAP * H + (size_t)m0 * H;
    const float* G = Wg + (size_t)e * H * F + n0;
    const float* U = Wu + (size_t)e * H * F + n0;

    int arow = tid >> 2, ac = (tid & 3) * 2;
    int bn = tid & 127, kh = tid >> 7;
    uint32_t a_r = wm * 32 + (lane & 15);
    uint32_t b_r = wn * 32 + (lane & 15);
    uint32_t chi = lane >> 4;

    float accG[2][4][4] = {};
    float accU[2][4][4] = {};
    uint32_t rg[8], ru[8];

    const int NS = H / 64;   // 16
    {
        uint32_t SA = sbuf, SBG = SA + GU_AST, SBU = SBG + GU_AST;
        CP16(SA + sw128(arow, ac),     A + (size_t)arow * H + ac * 8);
        CP16(SA + sw128(arow, ac + 1), A + (size_t)arow * H + ac * 8 + 8);
        CP_COMMIT();
        #pragma unroll
        for (int q = 0; q < 8; q++) {
            rg[q] = packh2(G[(size_t)(kh * 16 + 2 * q) * F + bn], G[(size_t)(kh * 16 + 2 * q + 1) * F + bn]);
            ru[q] = packh2(U[(size_t)(kh * 16 + 2 * q) * F + bn], U[(size_t)(kh * 16 + 2 * q + 1) * F + bn]);
        }
        STS128(SBG + sw128(bn, kh * 2),     rg[0], rg[1], rg[2], rg[3]);
        STS128(SBG + sw128(bn, kh * 2 + 1), rg[4], rg[5], rg[6], rg[7]);
        STS128(SBU + sw128(bn, kh * 2),     ru[0], ru[1], ru[2], ru[3]);
        STS128(SBU + sw128(bn, kh * 2 + 1), ru[4], ru[5], ru[6], ru[7]);
        CP_WAIT0();
        __syncthreads();
    }

    #pragma unroll 2
    for (int s = 0; s < NS; s++) {
        uint32_t SA = sbuf + (s & 1) * GU_STG;
        uint32_t SBG = SA + GU_AST, SBU = SBG + GU_AST;
        uint32_t SAn = sbuf + ((s + 1) & 1) * GU_STG;
        uint32_t SBGn = SAn + GU_AST, SBUn = SBGn + GU_AST;
        int k0 = (s + 1) * 64;

        if (s + 1 < NS) {
            CP16(SAn + sw128(arow, ac),     A + (size_t)arow * H + k0 + ac * 8);
            CP16(SAn + sw128(arow, ac + 1), A + (size_t)arow * H + k0 + ac * 8 + 8);
            CP_COMMIT();
            #pragma unroll
            for (int q = 0; q < 8; q++)
                rg[q] = packh2(G[(size_t)(k0 + kh * 16 + 2 * q) * F + bn], G[(size_t)(k0 + kh * 16 + 2 * q + 1) * F + bn]);
        }
        #pragma unroll
        for (int ks = 0; ks < 2; ks++) {
            uint32_t a[2][4], bg[2][4], bu[2][4];
            #pragma unroll
            for (int i = 0; i < 2; i++)
                LDSM4(a[i][0], a[i][1], a[i][2], a[i][3], SA + sw128(a_r + i * 16, ks * 2 + chi));
            #pragma unroll
            for (int j = 0; j < 2; j++) {
                LDSM4(bg[j][0], bg[j][1], bg[j][2], bg[j][3], SBG + sw128(b_r + j * 16, ks * 2 + chi));
                LDSM4(bu[j][0], bu[j][1], bu[j][2], bu[j][3], SBU + sw128(b_r + j * 16, ks * 2 + chi));
            }
            #pragma unroll
            for (int i = 0; i < 2; i++)
                #pragma unroll
                for (int j4 = 0; j4 < 4; j4++) {
                    MMA16(accG[i][j4], a[i], bg[j4 >> 1][j4 & 1], bg[j4 >> 1][(j4 & 1) + 2]);
                    MMA16(accU[i][j4], a[i], bu[j4 >> 1][j4 & 1], bu[j4 >> 1][(j4 & 1) + 2]);
                }
        }
        if (s + 1 < NS) {
            STS128(SBGn + sw128(bn, kh * 2),     rg[0], rg[1], rg[2], rg[3]);
            STS128(SBGn + sw128(bn, kh * 2 + 1), rg[4], rg[5], rg[6], rg[7]);
            #pragma unroll
            for (int q = 0; q < 8; q++)
                ru[q] = packh2(U[(size_t)(k0 + kh * 16 + 2 * q) * F + bn], U[(size_t)(k0 + kh * 16 + 2 * q + 1) * F + bn]);
        }
        #pragma unroll
        for (int ks = 2; ks < 4; ks++) {
            uint32_t a[2][4], bg[2][4], bu[2][4];
            #pragma unroll
            for (int i = 0; i < 2; i++)
                LDSM4(a[i][0], a[i][1], a[i][2], a[i][3], SA + sw128(a_r + i * 16, ks * 2 + chi));
            #pragma unroll
            for (int j = 0; j < 2; j++) {
                LDSM4(bg[j][0], bg[j][1], bg[j][2], bg[j][3], SBG + sw128(b_r + j * 16, ks * 2 + chi));
                LDSM4(bu[j][0], bu[j][1], bu[j][2], bu[j][3], SBU + sw128(b_r + j * 16, ks * 2 + chi));
            }
            #pragma unroll
            for (int i = 0; i < 2; i++)
                #pragma unroll
                for (int j4 = 0; j4 < 4; j4++) {
                    MMA16(accG[i][j4], a[i], bg[j4 >> 1][j4 & 1], bg[j4 >> 1][(j4 & 1) + 2]);
                    MMA16(accU[i][j4], a[i], bu[j4 >> 1][j4 & 1], bu[j4 >> 1][(j4 & 1) + 2]);
                }
        }
        if (s + 1 < NS) {
            STS128(SBUn + sw128(bn, kh * 2),     ru[0], ru[1], ru[2], ru[3]);
            STS128(SBUn + sw128(bn, kh * 2 + 1), ru[4], ru[5], ru[6], ru[7]);
        }
        CP_WAIT0();
        __syncthreads();
    }

    __half* Hd = g_hid + (size_t)e * CAP * F;
    int r0 = m0 + wm * 32 + (lane >> 2);
    int c0 = n0 + wn * 32 + (lane & 3) * 2;
    #pragma unroll
    for (int i = 0; i < 2; i++) {
        #pragma unroll
        for (int j = 0; j < 4; j++) {
            int r = r0 + i * 16, c = c0 + j * 8;
            if (r < cnt) {
                float g0 = accG[i][j][0], g1 = accG[i][j][1];
                *(uint32_t*)(Hd + (size_t)r * F + c) =
                    packh2(g0 / (1.f + __expf(-g0)) * accU[i][j][0],
                           g1 / (1.f + __expf(-g1)) * accU[i][j][1]);
            }
            if (r + 8 < cnt) {
                float g2 = accG[i][j][2], g3 = accG[i][j][3];
                *(uint32_t*)(Hd + (size_t)(r + 8) * F + c) =
                    packh2(g2 / (1.f + __expf(-g2)) * accU[i][j][2],
                           g3 / (1.f + __expf(-g3)) * accU[i][j][3]);
            }
        }
    }
}

// ---------------- down GEMM: warp 64x32, 2 CTAs/SM, split-K=2, fp16 partials ----------------
// Block 128(M)x128(N), 256 thr / 8 warps (2m x 4n), warp 64x32, KCH=64.
__global__ void __launch_bounds__(256, 2) down_mma(const float* __restrict__ Wd) {
    extern __shared__ char smem[];
    int e = blockIdx.z >> 1, kz = blockIdx.z & 1;
    int cnt = g_count[e];
    int m0 = blockIdx.y * 128;
    if (m0 >= cnt) return;
    int n0 = blockIdx.x * 128;
    uint32_t sbuf = (smem_u32(smem) + 127u) & ~127u;

    int tid = threadIdx.x, lane = tid & 31, wid = tid >> 5;
    int wm = wid >> 2, wn = wid & 3;

    const __half* A = g_hid + ((size_t)e * CAP + m0) * F + kz * (F / 2);
    const float*  W = Wd + (size_t)e * F * H + (size_t)kz * (F / 2) * H + n0;

    int arow = tid >> 1, ac = (tid & 1) * 4;
    int bn = tid & 127, kh = tid >> 7;
    uint32_t a_r = wm * 64 + (lane & 15);
    uint32_t b_r = wn * 32 + (lane & 15);
    uint32_t chi = lane >> 4;

    float acc[4][4][4] = {};
    uint32_t rb[8];

    const int NS = (F / 2) / 64;   // 16
    {
        uint32_t SA = sbuf, SB = SA + DN_AST;
        #pragma unroll
        for (int q = 0; q < 4; q++)
            CP16(SA + sw128(arow, ac + q), A + (size_t)arow * F + (ac + q) * 8);
        CP_COMMIT();
        #pragma unroll
        for (int q = 0; q < 8; q++)
            rb[q] = packh2(W[(size_t)(kh * 32 + 2 * q) * H + bn], W[(size_t)(kh * 32 + 2 * q + 1) * H + bn]);
        STS128(SB + sw128(bn, kh * 4),     rb[0], rb[1], rb[2], rb[3]);
        STS128(SB + sw128(bn, kh * 4 + 1), rb[4], rb[5], rb[6], rb[7]);
        #pragma unroll
        for (int q = 0; q < 8; q++)
            rb[q] = packh2(W[(size_t)(kh * 32 + 16 + 2 * q) * H + bn], W[(size_t)(kh * 32 + 17 + 2 * q) * H + bn]);
        STS128(SB + sw128(bn, kh * 4 + 2), rb[0], rb[1], rb[2], rb[3]);
        STS128(SB + sw128(bn, kh * 4 + 3), rb[4], rb[5], rb[6], rb[7]);
        CP_WAIT0();
        __syncthreads();
    }

    #pragma unroll 2
    for (int s = 0; s < NS; s++) {
        uint32_t SA = sbuf + (s & 1) * DN_STG, SB = SA + DN_AST;
        uint32_t SAn = sbuf + ((s + 1) & 1) * DN_STG, SBn = SAn + DN_AST;
        int k0 = (s + 1) * 64;

        if (s + 1 < NS) {
            #pragma unroll
            for (int q = 0; q < 4; q++)
                CP16(SAn + sw128(arow, ac + q), A + (size_t)arow * F + k0 + (ac + q) * 8);
            CP_COMMIT();
            #pragma unroll
            for (int q = 0; q < 8; q++)
                rb[q] = packh2(W[(size_t)(k0 + kh * 32 + 2 * q) * H + bn], W[(size_t)(k0 + kh * 32 + 2 * q + 1) * H + bn]);
        }
        #pragma unroll
        for (int ks = 0; ks < 2; ks++) {
            uint32_t a[4][4], bq[2][4];
            #pragma unroll
            for (int i = 0; i < 4; i++)
                LDSM4(a[i][0], a[i][1], a[i][2], a[i][3], SA + sw128(a_r + i * 16, ks * 2 + chi));
            #pragma unroll
            for (int j = 0; j < 2; j++)
                LDSM4(bq[j][0], bq[j][1], bq[j][2], bq[j][3], SB + sw128(b_r + j * 16, ks * 2 + chi));
            #pragma unroll
            for (int i = 0; i < 4; i++)
                #pragma unroll
                for (int j4 = 0; j4 < 4; j4++)
                    MMA16(acc[i][j4], a[i], bq[j4 >> 1][j4 & 1], bq[j4 >> 1][(j4 & 1) + 2]);
        }
        if (s + 1 < NS) {
            STS128(SBn + sw128(bn, kh * 4),     rb[0], rb[1], rb[2], rb[3]);
            STS128(SBn + sw128(bn, kh * 4 + 1), rb[4], rb[5], rb[6], rb[7]);
            #pragma unroll
            for (int q = 0; q < 8; q++)
                rb[q] = packh2(W[(size_t)(k0 + kh * 32 + 16 + 2 * q) * H + bn], W[(size_t)(k0 + kh * 32 + 17 + 2 * q) * H + bn]);
        }
        #pragma unroll
        for (int ks = 2; ks < 4; ks++) {
            uint32_t a[4][4], bq[2][4];
            #pragma unroll
            for (int i = 0; i < 4; i++)
                LDSM4(a[i][0], a[i][1], a[i][2], a[i][3], SA + sw128(a_r + i * 16, ks * 2 + chi));
            #pragma unroll
            for (int j = 0; j < 2; j++)
                LDSM4(bq[j][0], bq[j][1], bq[j][2], bq[j][3], SB + sw128(b_r + j * 16, ks * 2 + chi));
            #pragma unroll
            for (int i = 0; i < 4; i++)
                #pragma unroll
                for (int j4 = 0; j4 < 4; j4++)
                    MMA16(acc[i][j4], a[i], bq[j4 >> 1][j4 & 1], bq[j4 >> 1][(j4 & 1) + 2]);
        }
        if (s + 1 < NS) {
            STS128(SBn + sw128(bn, kh * 4 + 2), rb[0], rb[1], rb[2], rb[3]);
            STS128(SBn + sw128(bn, kh * 4 + 3), rb[4], rb[5], rb[6], rb[7]);
        }
        CP_WAIT0();
        __syncthreads();
    }

    __half* Y = (kz == 0 ? g_yh : g_yh2) + (size_t)e * CAP * H;
    int r0 = m0 + wm * 64 + (lane >> 2);
    int c0 = n0 + wn * 32 + (lane & 3) * 2;
    #pragma unroll
    for (int i = 0; i < 4; i++) {
        #pragma unroll
        for (int j = 0; j < 4; j++) {
            int r = r0 + i * 16, c = c0 + j * 8;
            if (r < cnt)
                *(uint32_t*)(Y + (size_t)r * H + c) = packh2(acc[i][j][0], acc[i][j][1]);
            if (r + 8 < cnt)
                *(uint32_t*)(Y + (size_t)(r + 8) * H + c) = packh2(acc[i][j][2], acc[i][j][3]);
        }
    }
}

// ---------------- combine (+ aux in extra block) ----------------
__global__ void combine_kernel(float* __restrict__ out, int do_aux) {
    if (blockIdx.x == T) {
        int tid = threadIdx.x, wid = tid >> 5, lane = tid & 31;
        __shared__ float part[E];
        #pragma unroll
        for (int ee = 0; ee < 4; ee++) {
            int e = wid * 4 + ee;
            float s = 0.f; int c = 0;
            for (int t = lane; t < T; t += 32) {
                s += g_probs[(size_t)t * E + e];
                c += (g_top1[t] == e) ? 1 : 0;
            }
            #pragma unroll
            for (int o = 16; o; o >>= 1) {
                s += __shfl_xor_sync(0xffffffffu, s, o);
                c += __shfl_xor_sync(0xffffffffu, c, o);
            }
            if (lane == 0) part[e] = (s / (float)T) * ((float)c / (float)T);
        }
        __syncthreads();
        if (tid == 0) {
            float a = 0.f;
            for (int i = 0; i < E; i++) a += part[i];
            out[(size_t)T * H] = a * (float)E * AUX_COEF;
        }
        return;
    }
    int t = blockIdx.x;
    int i0 = 2 * t, i1 = 2 * t + 1;
    int e0 = g_route_e[i0], e1 = g_route_e[i1];
    int k0 = g_route_keep[i0], k1 = g_route_keep[i1];
    int p0 = k0 ? g_route_pos[i0] : 0;
    int p1 = k1 ? g_route_pos[i1] : 0;
    float w0 = k0 ? g_route_w[i0] : 0.f;
    float w1 = k1 ? g_route_w[i1] : 0.f;
    size_t o0 = ((size_t)e0 * CAP + p0) * H;
    size_t o1 = ((size_t)e1 * CAP + p1) * H;
    float* o = out + (size_t)t * H;
    int h = threadIdx.x * 4;
    uint2 a0 = *(const uint2*)(g_yh + o0 + h);
    uint2 a1 = *(const uint2*)(g_yh2 + o0 + h);
    uint2 b0 = *(const uint2*)(g_yh + o1 + h);
    uint2 b1 = *(const uint2*)(g_yh2 + o1 + h);
    float2 a0x = __half22float2(*(__half2*)&a0.x), a0y = __half22float2(*(__half2*)&a0.y);
    float2 a1x = __half22float2(*(__half2*)&a1.x), a1y = __half22float2(*(__half2*)&a1.y);
    float2 b0x = __half22float2(*(__half2*)&b0.x), b0y = __half22float2(*(__half2*)&b0.y);
    float2 b1x = __half22float2(*(__half2*)&b1.x), b1y = __half22float2(*(__half2*)&b1.y);
    float4 r;
    r.x = w0 * (a0x.x + a1x.x) + w1 * (b0x.x + b1x.x);
    r.y = w0 * (a0x.y + a1x.y) + w1 * (b0x.y + b1x.y);
    r.z = w0 * (a0y.x + a1y.x) + w1 * (b0y.x + b1y.x);
    r.w = w0 * (a0y.y + a1y.y) + w1 * (b0y.y + b1y.y);
    *(float4*)(o + h) = r;
}

// ---------------- launch ----------------
extern "C" void kernel_launch(void* const* d_in, const int* in_sizes, int n_in,
                              void* d_out, int out_size) {
    const float* x  = (const float*)d_in[0];
    const float* Wr = (const float*)d_in[1];
    const float* br = (const float*)d_in[2];
    const float* Wg = (const float*)d_in[3];
    const float* Wu = (const float*)d_in[4];
    const float* Wd = (const float*)d_in[5];
    float* out = (float*)d_out;

    int gu_sm = 2 * GU_STG + 128;   // 96KB
    int dn_sm = 2 * DN_STG + 128;   // 64KB -> 2 CTAs/SM
    int rsm = RT * H * 4;
    cudaFuncSetAttribute(gu_mma, cudaFuncAttributeMaxDynamicSharedMemorySize, gu_sm);
    cudaFuncSetAttribute(down_mma, cudaFuncAttributeMaxDynamicSharedMemorySize, dn_sm);
    cudaFuncSetAttribute(router_kernel, cudaFuncAttributeMaxDynamicSharedMemorySize, rsm);

    router_kernel<<<T / RT, 256, rsm>>>(x, Wr, br);
    dispatch_kernel<<<1, 1024>>>();
    gather_kernel<<<T * KSEL, 256>>>(x);

    dim3 gu_grid(F / 128, CAP / 128, E);
    gu_mma<<<gu_grid, 512, gu_sm>>>(Wg, Wu);

    dim3 dn_grid(H / 128, CAP / 128, E * 2);
    down_mma<<<dn_grid, 256, dn_sm>>>(Wd);

    int do_aux = (out_size > T * H) ? 1 : 0;
    combine_kernel<<<T + do_aux, 256>>>(out, do_aux);
}